// round 16
// baseline (speedup 1.0000x reference)
#include <cuda_runtime.h>

// BoxLoss: 3-scale YOLO box loss. ONE launch, 32 blocks (1 image each),
// 192 threads = 3 scale groups x 64 lanes. Final structure (R14 skeleton):
//  - targets LDG first (gates the chain); anchors off-path
//  - prefetch.global.L2 of all 3 candidate cells before the IoU; the
//    single best-anchor demand gather MSHR-merges with it (measured best;
//    3-cell register gathers regress — R4/R15)
//  - count exchange (ballot/STS/bar/LDS) hoisted BEFORE contrib so the
//    barrier overlaps the gather's in-flight window
//  - inv2n divide hoisted before the warp reduce (overlaps the shfl chain)
//  - tail: per-warp fixed-point publish via ONE global counting atomicAdd;
//    the 192nd arriver holds the exact integer total in registers.
//    Integer accumulation -> associative -> deterministic.

#define NT   50
#define NA   3
#define NC   85
#define BMAX 32
#define THRESH 0.5f
#define FULL 0xffffffffu
#define FIXF 1073741824.0f           // 2^30 exact in float
#define FIX  1073741824.0
#define GTAG (1ull << 56)
#define GVAL ((1ull << 56) - 1ull)

__device__ unsigned long long g_acc = 0ull;

__device__ __forceinline__ void st_cg64(unsigned long long* p, unsigned long long v) {
    asm volatile("st.global.cg.u64 [%0], %1;" :: "l"(p), "l"(v) : "memory");
}
__device__ __forceinline__ void prefetch_l2(const void* p) {
    asm volatile("prefetch.global.L2 [%0];" :: "l"(p));
}

__global__ void __launch_bounds__(192, 1)
box_loss_fused(const float* __restrict__ out0, const float* __restrict__ anc0,
               const float* __restrict__ out1, const float* __restrict__ anc1,
               const float* __restrict__ out2, const float* __restrict__ anc2,
               const float* __restrict__ targets,
               float* __restrict__ result, float invB)
{
    const int b    = blockIdx.x;
    const int B    = gridDim.x;
    const int tid  = threadIdx.x;
    const int g    = tid >> 6;          // scale group 0..2
    const int l    = tid & 63;          // lane in group (== target index)
    const int lane = tid & 31;
    const int wid  = tid >> 5;          // 0..5
    const bool odd = (l >= 32);

    __shared__ int skey18[3][18];       // warp-odd keys (targets 32..49)
    __shared__ int scnt[6];             // per-warp winner counts

    const float* out = (g == 0) ? out0 : (g == 1) ? out1 : out2;
    const float* anc = (g == 0) ? anc0 : (g == 1) ? anc1 : anc2;
    const int    G   = (g == 0) ? 52   : (g == 1) ? 26   : 13;
    const float  fG  = (float)G;

    // ---- targets first: they gate the whole chain ----
    float x = 0.f, y = 0.f, w = 0.f, h = 0.f;
    if (l < NT) {
        const float* tg = targets + ((size_t)b * NT + l) * 5;
        x = __ldg(tg + 1); y = __ldg(tg + 2);
        w = __ldg(tg + 3); h = __ldg(tg + 4);
    }
    // anchors: independent, needed only at the IoU
    const float aw0 = __ldg(anc + 0), ah0 = __ldg(anc + 1);
    const float aw1 = __ldg(anc + 2), ah1 = __ldg(anc + 3);
    const float aw2 = __ldg(anc + 4), ah2 = __ldg(anc + 5);

    const bool  valid = (l < NT) && !(x == 0.f && y == 0.f && w == 0.f && h == 0.f);
    const float tx = x * fG, ty = y * fG, tw = w * fG, th = h * fG;
    const float cx = floorf(tx), cy = floorf(ty);
    const int   icx = (int)cx,   icy = (int)cy;
    const bool  inb = valid && icx >= 0 && icx < G && icy >= 0 && icy < G;

    // ---- prefetch all 3 candidate cells into L2 before the IoU ----
    const long long cellbase = (((long long)b * NA) * G + icy) * G + icx;
    if (inb) {
        prefetch_l2(out + (cellbase + 0 * (long long)G * G) * NC);
        prefetch_l2(out + (cellbase + 1 * (long long)G * G) * NC);
        prefetch_l2(out + (cellbase + 2 * (long long)G * G) * NC);
    }

    // ---- IoU vs 3 anchors (areas from rect diffs, matching reference) ----
    const float zx = tx - cx - 0.5f, zy = ty - cy - 0.5f;
    const float t0 = zx - tw * 0.5f, t1 = zy - th * 0.5f;
    const float t2 = zx + tw * 0.5f, t3 = zy + th * 0.5f;
    const float area_t = (t2 - t0) * (t3 - t1);

    float overlap = -1.f;
    int   best = 0;
    #pragma unroll
    for (int a = 0; a < NA; a++) {
        const float w2 = ((a == 0) ? aw0 : (a == 1) ? aw1 : aw2) * 0.5f;
        const float h2 = ((a == 0) ? ah0 : (a == 1) ? ah1 : ah2) * 0.5f;
        const float x0 = fmaxf(t0, -w2), y0 = fmaxf(t1, -h2);
        const float x1 = fminf(t2,  w2), y1 = fminf(t3,  h2);
        const float inter  = (x0 < x1 && y0 < y1) ? (x1 - x0) * (y1 - y0) : 0.f;
        const float area_a = (2.f * w2) * (2.f * h2);
        const float iou = inter / (area_t + area_a - inter);
        if (iou > overlap) { overlap = iou; best = a; }   // first-max wins
    }

    const int key = (inb && overlap > THRESH) ? (best * G + icy) * G + icx : -1;

    // ---- producer: odd warp exports keys, arrives (non-blocking) ----
    if (odd) {
        if (l < NT) skey18[g][l - 32] = key;
        asm volatile("bar.arrive %0, 64;" :: "r"(g + 1) : "memory");
    }

    // ---- demand gather (best anchor only) — merges with the L2 prefetch ----
    float px = 0.f, py = 0.f, pw = 1.f, ph = 1.f;
    if (key >= 0) {
        const float* c = out + (cellbase + (long long)best * G * G) * (long long)NC;
        px = __ldg(c + 0); py = __ldg(c + 1);
        pw = __ldg(c + 2); ph = __ldg(c + 3);
    }

    // ---- dup resolution: last target index wins ----
    const unsigned mmask = __match_any_sync(FULL, key);
    bool win = (key >= 0) && ((31 - __clz(mmask)) == lane);
    if (!odd) {
        asm volatile("bar.sync %0, 64;" :: "r"(g + 1) : "memory");
        if (win) {
            bool dup = false;
            #pragma unroll
            for (int j = 0; j < 18; j++)
                dup |= (skey18[g][j] == key);
            win = !dup;
        }
    }

    // ---- count exchange FIRST (doesn't need gather data): the barrier
    //      overlaps the gather's remaining in-flight window ----
    const int cnt = __popc(__ballot_sync(FULL, win));
    if (lane == 0) scnt[wid] = cnt;
    asm volatile("bar.sync %0, 64;" :: "r"(g + 4) : "memory");
    const int n = scnt[wid] + scnt[wid ^ 1];          // group winner count
    // hoist the divide: overlaps the shfl reduce below
    const float inv2n = (n > 0) ? __fdividef(1.0f, 2.0f * (float)n) : 0.f;

    // ---- contrib (gather data has arrived by now) ----
    float contrib = 0.f;
    if (win) {
        const float dx = px - tx, dy = py - ty;
        const float rw = rsqrtf(pw) - rsqrtf(tw);
        const float rh = rsqrtf(ph) - rsqrtf(th);
        contrib = dx * dx + dy * dy + rw * rw + rh * rh;
    }

    // ---- warp reduce ----
    float sum = contrib;
    #pragma unroll
    for (int off = 16; off > 0; off >>= 1)
        sum += __shfl_down_sync(FULL, sum, off);

    // ---- per-warp publish: warpsum/(2n) as fixed-point, ONE counting atomic
    if (lane == 0) {
        const long long fix = (long long)(sum * inv2n * FIXF);
        const unsigned long long gpack = GTAG | (unsigned long long)fix;
        const unsigned long long gold  = atomicAdd(&g_acc, gpack);
        if ((gold >> 56) == (unsigned long long)(6 * B - 1)) {
            // 192nd arrival: exact integer total already in registers
            const unsigned long long gtot = gold + gpack;
            const double s = (double)(long long)(gtot & GVAL) * (1.0 / FIX);
            result[0] = (float)s * invB;
            st_cg64(&g_acc, 0ull);               // re-arm for next replay
        }
    }
}

extern "C" void kernel_launch(void* const* d_in, const int* in_sizes, int n_in,
                              void* d_out, int out_size)
{
    const float* out0 = (const float*)d_in[0];
    const float* anc0 = (const float*)d_in[1];
    const float* out1 = (const float*)d_in[2];
    const float* anc1 = (const float*)d_in[3];
    const float* out2 = (const float*)d_in[4];
    const float* anc2 = (const float*)d_in[5];
    const float* tgts = (const float*)d_in[6];

    int B = in_sizes[6] / (NT * 5);
    if (B > BMAX) B = BMAX;

    box_loss_fused<<<B, 192>>>(out0, anc0, out1, anc1, out2, anc2, tgts,
                               (float*)d_out, 1.0f / (float)B);
}

// round 17
// speedup vs baseline: 1.0386x; 1.0386x over previous
#include <cuda_runtime.h>

// BoxLoss: 3-scale YOLO box loss — FINAL (R14 configuration, measured best).
// ONE launch, 32 blocks (1 image each), 192 threads = 3 scale groups x 64.
//  - targets LDG first (gates the chain); anchors off the critical path
//  - prefetch.global.L2 of all 3 candidate cells before the IoU; the single
//    best-anchor demand gather MSHR-merges with the in-flight prefetch
//    (measured best: full 3-cell register gathers regress — R4/R15)
//  - dup resolution: __match_any_sync intra-warp (highest lane = highest
//    target index wins) + 18-key smem check for the lo half; odd warp
//    arrives non-blocking, only even warp bar.syncs
//  - tail: per-warp loss share warpsum/(2n) as 2^30 fixed-point, published
//    through ONE global counting atomicAdd; the 192nd arriver holds the
//    exact integer total in registers and writes the scalar, then re-arms.
//    Integer accumulation -> associative -> bit-deterministic.

#define NT   50
#define NA   3
#define NC   85
#define BMAX 32
#define THRESH 0.5f
#define FULL 0xffffffffu
#define FIXF 1073741824.0f           // 2^30 exact in float
#define FIX  1073741824.0
#define GTAG (1ull << 56)
#define GVAL ((1ull << 56) - 1ull)

__device__ unsigned long long g_acc = 0ull;

__device__ __forceinline__ void st_cg64(unsigned long long* p, unsigned long long v) {
    asm volatile("st.global.cg.u64 [%0], %1;" :: "l"(p), "l"(v) : "memory");
}
__device__ __forceinline__ void prefetch_l2(const void* p) {
    asm volatile("prefetch.global.L2 [%0];" :: "l"(p));
}

__global__ void __launch_bounds__(192, 1)
box_loss_fused(const float* __restrict__ out0, const float* __restrict__ anc0,
               const float* __restrict__ out1, const float* __restrict__ anc1,
               const float* __restrict__ out2, const float* __restrict__ anc2,
               const float* __restrict__ targets,
               float* __restrict__ result, float invB)
{
    const int b    = blockIdx.x;
    const int B    = gridDim.x;
    const int tid  = threadIdx.x;
    const int g    = tid >> 6;          // scale group 0..2
    const int l    = tid & 63;          // lane in group (== target index)
    const int lane = tid & 31;
    const int wid  = tid >> 5;          // 0..5
    const bool odd = (l >= 32);

    __shared__ int skey18[3][18];       // warp-odd keys (targets 32..49)
    __shared__ int scnt[6];             // per-warp winner counts

    const float* out = (g == 0) ? out0 : (g == 1) ? out1 : out2;
    const float* anc = (g == 0) ? anc0 : (g == 1) ? anc1 : anc2;
    const int    G   = (g == 0) ? 52   : (g == 1) ? 26   : 13;
    const float  fG  = (float)G;

    // ---- targets first: they gate the whole chain ----
    float x = 0.f, y = 0.f, w = 0.f, h = 0.f;
    if (l < NT) {
        const float* tg = targets + ((size_t)b * NT + l) * 5;
        x = __ldg(tg + 1); y = __ldg(tg + 2);
        w = __ldg(tg + 3); h = __ldg(tg + 4);
    }
    // anchors: independent, needed only ~600cy later at the IoU
    const float aw0 = __ldg(anc + 0), ah0 = __ldg(anc + 1);
    const float aw1 = __ldg(anc + 2), ah1 = __ldg(anc + 3);
    const float aw2 = __ldg(anc + 4), ah2 = __ldg(anc + 5);

    const bool  valid = (l < NT) && !(x == 0.f && y == 0.f && w == 0.f && h == 0.f);
    const float tx = x * fG, ty = y * fG, tw = w * fG, th = h * fG;
    const float cx = floorf(tx), cy = floorf(ty);
    const int   icx = (int)cx,   icy = (int)cy;
    const bool  inb = valid && icx >= 0 && icx < G && icy >= 0 && icy < G;

    // ---- prefetch all 3 candidate cells into L2 NOW (before the IoU);
    //      the demand load below MSHR-merges with these in-flight lines ----
    const long long cellbase = (((long long)b * NA) * G + icy) * G + icx;
    if (inb) {
        prefetch_l2(out + (cellbase + 0 * (long long)G * G) * NC);
        prefetch_l2(out + (cellbase + 1 * (long long)G * G) * NC);
        prefetch_l2(out + (cellbase + 2 * (long long)G * G) * NC);
    }

    // ---- IoU vs 3 anchors (areas from rect diffs, matching reference) ----
    const float zx = tx - cx - 0.5f, zy = ty - cy - 0.5f;
    const float t0 = zx - tw * 0.5f, t1 = zy - th * 0.5f;
    const float t2 = zx + tw * 0.5f, t3 = zy + th * 0.5f;
    const float area_t = (t2 - t0) * (t3 - t1);

    float overlap = -1.f;
    int   best = 0;
    #pragma unroll
    for (int a = 0; a < NA; a++) {
        const float w2 = ((a == 0) ? aw0 : (a == 1) ? aw1 : aw2) * 0.5f;
        const float h2 = ((a == 0) ? ah0 : (a == 1) ? ah1 : ah2) * 0.5f;
        const float x0 = fmaxf(t0, -w2), y0 = fmaxf(t1, -h2);
        const float x1 = fminf(t2,  w2), y1 = fminf(t3,  h2);
        const float inter  = (x0 < x1 && y0 < y1) ? (x1 - x0) * (y1 - y0) : 0.f;
        const float area_a = (2.f * w2) * (2.f * h2);
        const float iou = inter / (area_t + area_a - inter);
        if (iou > overlap) { overlap = iou; best = a; }   // first-max wins
    }

    const int key = (inb && overlap > THRESH) ? (best * G + icy) * G + icx : -1;

    // ---- producer: odd warp exports keys, arrives (non-blocking) ----
    if (odd) {
        if (l < NT) skey18[g][l - 32] = key;
        asm volatile("bar.arrive %0, 64;" :: "r"(g + 1) : "memory");
    }

    // ---- demand gather (best anchor only) — merges with the L2 prefetch ----
    float px = 0.f, py = 0.f, pw = 1.f, ph = 1.f;
    if (key >= 0) {
        const float* c = out + (cellbase + (long long)best * G * G) * (long long)NC;
        px = __ldg(c + 0); py = __ldg(c + 1);
        pw = __ldg(c + 2); ph = __ldg(c + 3);
    }

    // ---- dup resolution: last target index wins ----
    const unsigned mmask = __match_any_sync(FULL, key);
    bool win = (key >= 0) && ((31 - __clz(mmask)) == lane);
    if (!odd) {
        asm volatile("bar.sync %0, 64;" :: "r"(g + 1) : "memory");
        if (win) {
            bool dup = false;
            #pragma unroll
            for (int j = 0; j < 18; j++)
                dup |= (skey18[g][j] == key);
            win = !dup;
        }
    }

    float contrib = 0.f;
    if (win) {
        const float dx = px - tx, dy = py - ty;
        const float rw = rsqrtf(pw) - rsqrtf(tw);
        const float rh = rsqrtf(ph) - rsqrtf(th);
        contrib = dx * dx + dy * dy + rw * rw + rh * rh;
    }

    // ---- exchange ONLY the counts across the warp pair ----
    const int cnt = __popc(__ballot_sync(FULL, win));
    if (lane == 0) scnt[wid] = cnt;
    asm volatile("bar.sync %0, 64;" :: "r"(g + 4) : "memory");

    // ---- warp reduce (overlaps the other warp's straggle) ----
    float sum = contrib;
    #pragma unroll
    for (int off = 16; off > 0; off >>= 1)
        sum += __shfl_down_sync(FULL, sum, off);

    // ---- per-warp publish: warpsum/(2n) as fixed-point, ONE counting atomic
    if (lane == 0) {
        const int n = scnt[wid] + scnt[wid ^ 1];     // group count
        long long fix = 0ll;
        if (n > 0)
            fix = (long long)(__fdividef(sum, 2.0f * (float)n) * FIXF);
        const unsigned long long gpack = GTAG | (unsigned long long)fix;
        const unsigned long long gold  = atomicAdd(&g_acc, gpack);
        if ((gold >> 56) == (unsigned long long)(6 * B - 1)) {
            // 192nd arrival: exact integer total already in registers
            const unsigned long long gtot = gold + gpack;
            const double s = (double)(long long)(gtot & GVAL) * (1.0 / FIX);
            result[0] = (float)s * invB;
            st_cg64(&g_acc, 0ull);               // re-arm for next replay
        }
    }
}

extern "C" void kernel_launch(void* const* d_in, const int* in_sizes, int n_in,
                              void* d_out, int out_size)
{
    const float* out0 = (const float*)d_in[0];
    const float* anc0 = (const float*)d_in[1];
    const float* out1 = (const float*)d_in[2];
    const float* anc1 = (const float*)d_in[3];
    const float* out2 = (const float*)d_in[4];
    const float* anc2 = (const float*)d_in[5];
    const float* tgts = (const float*)d_in[6];

    int B = in_sizes[6] / (NT * 5);
    if (B > BMAX) B = BMAX;

    box_loss_fused<<<B, 192>>>(out0, anc0, out1, anc1, out2, anc2, tgts,
                               (float*)d_out, 1.0f / (float)B);
}